// round 3
// baseline (speedup 1.0000x reference)
#include <cuda_runtime.h>

#define THRESH 0.85f
#define NB 4
#define ND 16
#define NN 4096
#define CHUNK 512
#define NSTEP 32
#define STEPS (CHUNK / NSTEP)   // 16

typedef unsigned long long u64;

// transposed seg: [b][n][d], d contiguous (1 MB scratch)
__device__ float g_segT[NB * NN * ND];

__device__ __forceinline__ void ffma2(u64& acc, u64 a, u64 b) {
    asm("fma.rn.f32x2 %0, %1, %2, %0;" : "+l"(acc) : "l"(a), "l"(b));
}
__device__ __forceinline__ u64 pack2(float lo, float hi) {
    u64 r; asm("mov.b64 %0, {%1, %2};" : "=l"(r) : "f"(lo), "f"(hi)); return r;
}
__device__ __forceinline__ float2 unpack2(u64 v) {
    float2 f; asm("mov.b64 {%0, %1}, %2;" : "=f"(f.x), "=f"(f.y) : "l"(v)); return f;
}
__device__ __forceinline__ u64 add2(u64 a, u64 b) {
    u64 r; asm("add.rn.f32x2 %0, %1, %2;" : "=l"(r) : "l"(a), "l"(b)); return r;
}

// ---------------- prologue: seg [b][d][n] -> segT [b][n][d] ----------------
__global__ void __launch_bounds__(256) seg_transpose_kernel(const float* __restrict__ seg) {
    int idx = blockIdx.x * blockDim.x + threadIdx.x;   // 0 .. NB*NN-1
    int b = idx >> 12;
    int n = idx & (NN - 1);
    float vals[ND];
#pragma unroll
    for (int d = 0; d < ND; ++d)
        vals[d] = seg[(((size_t)b * ND + d) << 12) + n];
    float4* dst = reinterpret_cast<float4*>(g_segT + (size_t)idx * ND);
#pragma unroll
    for (int q = 0; q < 4; ++q)
        dst[q] = make_float4(vals[4*q], vals[4*q+1], vals[4*q+2], vals[4*q+3]);
}

// ---------------- main kernel ----------------
struct WBuf { float4 v[4]; };   // this lane's 4 n-values for each of its 4 rows

__device__ __forceinline__ void loadW(WBuf& wb, const float* p, int n) {
#pragma unroll
    for (int r = 0; r < 4; ++r)
        wb.v[r] = __ldg(reinterpret_cast<const float4*>(p + (size_t)r * NN + n));
}

// acc[r][0..7] = 16 d-sums (f32x2), acc[r][8].lo = rowsum, for 4 rows.
__device__ __forceinline__ void computeSS(const WBuf& wb, u64 (&acc)[4][9],
                                          const char* ssegB, int nloc, int j, u64 ones) {
#pragma unroll
    for (int k = 0; k < 4; ++k) {
        const int n = nloc + 4 * j + k;                 // local n within chunk
        const unsigned ofs = ((unsigned)n << 6) ^ ((unsigned)j << 4);  // swizzled byte offset
        ulonglong2 s0 = *reinterpret_cast<const ulonglong2*>(ssegB + (ofs ^ 0u));
        ulonglong2 s1 = *reinterpret_cast<const ulonglong2*>(ssegB + (ofs ^ 16u));
        ulonglong2 s2 = *reinterpret_cast<const ulonglong2*>(ssegB + (ofs ^ 32u));
        ulonglong2 s3 = *reinterpret_cast<const ulonglong2*>(ssegB + (ofs ^ 48u));
#pragma unroll
        for (int r = 0; r < 4; ++r) {
            float w = reinterpret_cast<const float*>(&wb.v[r])[k];
            float wt = (w > THRESH) ? w : 0.0f;
            u64 a = pack2(wt, wt);
            ffma2(acc[r][0], a, s0.x);
            ffma2(acc[r][1], a, s0.y);
            ffma2(acc[r][2], a, s1.x);
            ffma2(acc[r][3], a, s1.y);
            ffma2(acc[r][4], a, s2.x);
            ffma2(acc[r][5], a, s2.y);
            ffma2(acc[r][6], a, s3.x);
            ffma2(acc[r][7], a, s3.y);
            ffma2(acc[r][8], a, ones);   // rowsum in .lo
        }
    }
}

__device__ __forceinline__ void storeRow(const u64 (&a)[9], float* out, int b, int m) {
    float2 s8 = unpack2(a[8]);
    const float inv = 1.0f / s8.x;
    float* ob = out + (size_t)b * ND * NN + m;
#pragma unroll
    for (int i = 0; i < 8; ++i) {
        float2 f = unpack2(a[i]);
        ob[(size_t)(2*i)     * NN] = f.x * inv;
        ob[(size_t)(2*i + 1) * NN] = f.y * inv;
    }
}

// grid = 256 blocks (4 b * 64 row-tiles of 64 rows), block = 128 threads.
// Warp = 4 groups of 8 lanes; group g owns 4 rows; lane j owns n-offsets
// 4j..4j+3 of each 32-n superstep. LDG.128 per instr: 4 groups x 128B
// contiguous = 4 lines (wavefront floor). Each lane's 64B seg read is now
// amortized over 4 rows (halves LDS traffic vs R=2).
__global__ void __launch_bounds__(128, 2) regu_main_kernel(const float* __restrict__ W,
                                                           float* __restrict__ out) {
    __shared__ __align__(1024) float sseg[CHUNK * ND];   // 32KB, XOR-swizzled 16B slots
    const int tid  = threadIdx.x;
    const int warp = tid >> 5;
    const int lane = tid & 31;
    const int g    = lane >> 3;
    const int j    = lane & 7;
    const int b    = blockIdx.x >> 6;
    const int r0   = ((blockIdx.x & 63) << 6) + warp * 16 + g * 4;

    const float* p = W + ((size_t)b * NN + r0) * NN + j * 4;

    u64 acc[4][9];
#pragma unroll
    for (int r = 0; r < 4; ++r)
#pragma unroll
        for (int i = 0; i < 9; ++i) acc[r][i] = 0ull;
    const u64 ones = pack2(1.0f, 0.0f);

    const char* ssegB = reinterpret_cast<const char*>(sseg);

    WBuf b0, b1, b2, b3;
    loadW(b0, p, 0);        // prefetch depth 2 (supersteps 0 and 1)
    loadW(b1, p, NSTEP);

    for (int ch = 0; ch < NN / CHUNK; ++ch) {
        __syncthreads();
        // stage seg chunk with XOR swizzle: slot s = n*4+q -> phys = s ^ ((s>>4)&7)
        const float4* segTb =
            reinterpret_cast<const float4*>(g_segT + ((size_t)b * NN + ch * CHUNK) * ND);
#pragma unroll
        for (int i = 0; i < (CHUNK * 4) / 128; ++i) {
            int s = i * 128 + tid;
            float4 v = segTb[s];
            int phys = s ^ ((s >> 4) & 7);
            *reinterpret_cast<float4*>(const_cast<char*>(ssegB) + ((size_t)phys << 4)) = v;
        }
        __syncthreads();

        const int base = ch * CHUNK;
#pragma unroll 1
        for (int s = 0; s < STEPS; s += 4) {
            int n2 = base + (s + 2) * NSTEP; if (n2 >= NN) n2 = 0;
            loadW(b2, p, n2);
            computeSS(b0, acc, ssegB, (s + 0) * NSTEP, j, ones);
            int n3 = base + (s + 3) * NSTEP; if (n3 >= NN) n3 = 0;
            loadW(b3, p, n3);
            computeSS(b1, acc, ssegB, (s + 1) * NSTEP, j, ones);
            int n4 = base + (s + 4) * NSTEP; if (n4 >= NN) n4 = 0;
            loadW(b0, p, n4);
            computeSS(b2, acc, ssegB, (s + 2) * NSTEP, j, ones);
            int n5 = base + (s + 5) * NSTEP; if (n5 >= NN) n5 = 0;
            loadW(b1, p, n5);
            computeSS(b3, acc, ssegB, (s + 3) * NSTEP, j, ones);
        }
    }

    // reduce over the 8 lanes of each group (xor 1,2,4 stays within the group)
#pragma unroll
    for (int m = 1; m <= 4; m <<= 1) {
#pragma unroll
        for (int r = 0; r < 4; ++r)
#pragma unroll
            for (int i = 0; i < 9; ++i)
                acc[r][i] = add2(acc[r][i], __shfl_xor_sync(0xffffffffu, acc[r][i], m));
    }

    // lanes j=0..3 of each group write rows r0..r0+3
    if (j == 0)      storeRow(acc[0], out, b, r0);
    else if (j == 1) storeRow(acc[1], out, b, r0 + 1);
    else if (j == 2) storeRow(acc[2], out, b, r0 + 2);
    else if (j == 3) storeRow(acc[3], out, b, r0 + 3);
}

extern "C" void kernel_launch(void* const* d_in, const int* in_sizes, int n_in,
                              void* d_out, int out_size) {
    const float* seg = (const float*)d_in[0];   // [4,16,64,64] fp32
    const float* W   = (const float*)d_in[1];   // [4,4096,4096] fp32
    float* out = (float*)d_out;                 // [4,16,64,64] fp32
    (void)in_sizes; (void)n_in; (void)out_size;

    seg_transpose_kernel<<<(NB * NN) / 256, 256>>>(seg);
    regu_main_kernel<<<256, 128>>>(W, out);
}